// round 2
// baseline (speedup 1.0000x reference)
#include <cuda_runtime.h>

// BuiltSWAP on qubits A=0, B=7 of a 13-qubit state, batch 64.
// Reference: state @ M where M is the SWAP permutation matrix.
// With the bit-index flip in _swap_matrix: a -> 12, b -> 5.
// M[i, swap_bits(i)] = 1  =>  out[b, j] = state[b, swap_bits(j)]
// (SWAP is an involution). Pure permutation gather; M (256 MB) is ignored.
//
// Round-1 evidence (illegal access with a 4 MB interleaved write) implies the
// output buffer is 2 MB = 524288 float32 elements: the pipeline coerced the
// complex64 reference to float32, which keeps only the REAL part. So the
// expected output is just a permutation of state_re. We branch on out_size so
// both interpretations are handled and no write can go out of bounds.

#define NUM_QUBITS 13
#define NSTATE (1 << NUM_QUBITS)   // 8192
#define BIT_HI 12
#define BIT_LO 5
#define SWAP_MASK ((1u << BIT_HI) | (1u << BIT_LO))  // 0x1020

__device__ __forceinline__ unsigned swap_src(unsigned j) {
    unsigned bit_hi = (j >> BIT_HI) & 1u;
    unsigned bit_lo = (j >> BIT_LO) & 1u;
    return (bit_hi != bit_lo) ? (j ^ SWAP_MASK) : j;
}

// Real-part-only output: out[b*N + j] = re[b*N + swap_src(j)].
// Each thread moves 4 consecutive j (float4). Bits 5 and 12 are constant
// within any 4-aligned group, so source is also contiguous/aligned.
__global__ void __launch_bounds__(256)
swap_gate_real_kernel(const float* __restrict__ state_re,
                      float* __restrict__ out,
                      unsigned total4)   // number of float4 elements
{
    unsigned t = blockIdx.x * blockDim.x + threadIdx.x;
    if (t >= total4) return;
    unsigned e4 = t * 4u;
    unsigned b = e4 >> NUM_QUBITS;
    unsigned j = e4 & (NSTATE - 1u);
    unsigned src = swap_src(j);
    float4 re = *reinterpret_cast<const float4*>(state_re + b * NSTATE + src);
    *reinterpret_cast<float4*>(out + e4) = re;
}

// Interleaved complex64 output: out[2*(b*N+j)] = re, out[2*(b*N+j)+1] = im.
__global__ void __launch_bounds__(256)
swap_gate_cplx_kernel(const float* __restrict__ state_re,
                      const float* __restrict__ state_im,
                      float* __restrict__ out,
                      unsigned total4)   // number of 4-complex groups
{
    unsigned t = blockIdx.x * blockDim.x + threadIdx.x;
    if (t >= total4) return;
    unsigned e4 = t * 4u;
    unsigned b = e4 >> NUM_QUBITS;
    unsigned j = e4 & (NSTATE - 1u);
    unsigned src = swap_src(j);
    unsigned in_off = b * NSTATE + src;
    float4 re = *reinterpret_cast<const float4*>(state_re + in_off);
    float4 im = *reinterpret_cast<const float4*>(state_im + in_off);
    float4 o0 = make_float4(re.x, im.x, re.y, im.y);
    float4 o1 = make_float4(re.z, im.z, re.w, im.w);
    unsigned out_off = e4 * 2u;
    *reinterpret_cast<float4*>(out + out_off)     = o0;
    *reinterpret_cast<float4*>(out + out_off + 4) = o1;
}

extern "C" void kernel_launch(void* const* d_in, const int* in_sizes, int n_in,
                              void* d_out, int out_size)
{
    const float* state_re = (const float*)d_in[0];
    const float* state_im = (const float*)d_in[1];
    float* out = (float*)d_out;

    const int n = in_sizes[0];           // 64 * 8192 = 524288 state elements
    const int threads = 256;

    if (out_size >= 2 * n) {
        // Output holds interleaved complex floats (or complex64 elements
        // counted as >= 2n — either way 2n float writes fit).
        unsigned total4 = (unsigned)(n / 4);               // 4 complex per thread
        unsigned blocks = (total4 + threads - 1) / threads;
        swap_gate_cplx_kernel<<<blocks, threads>>>(state_re, state_im, out, total4);
    } else {
        // Output is n float32 elements: real part only.
        unsigned total4 = (unsigned)(out_size / 4);        // 4 floats per thread
        unsigned blocks = (total4 + threads - 1) / threads;
        swap_gate_real_kernel<<<blocks, threads>>>(state_re, out, total4);
    }
}

// round 3
// speedup vs baseline: 2.0545x; 2.0545x over previous
#include <cuda_runtime.h>

// BuiltSWAP on qubits A=0, B=7 of a 13-qubit state, batch 64.
// Reference computes state @ M (M = SWAP permutation matrix); after the
// bit-index flip in _swap_matrix this is out[b, j] = state[b, swap_bits(j)]
// with bits 12 and 5 exchanged (SWAP is an involution). The harness output
// buffer is n float32 (complex64 reference coerced to float32 = real part),
// so only state_re is permuted; state_im and M (256 MB) are dead inputs.
//
// Latency-bound at this size (4 MB traffic): grid-stride with 4 front-batched
// independent float4 loads per thread to raise MLP, no bounds checks
// (524288 / 4 / 256 / 128 divides exactly).

#define NUM_QUBITS 13
#define NSTATE (1 << NUM_QUBITS)   // 8192
#define BIT_HI 12
#define BIT_LO 5
#define SWAP_MASK ((1u << BIT_HI) | (1u << BIT_LO))  // 0x1020

#define THREADS 256
#define BLOCKS 128
#define UNROLL 4
// BLOCKS*THREADS*UNROLL float4s = 131072 = 524288 floats. Exact.

__device__ __forceinline__ unsigned swap_src(unsigned j) {
    // j with bits 12 and 5 exchanged.
    unsigned bit_hi = (j >> BIT_HI) & 1u;
    unsigned bit_lo = (j >> BIT_LO) & 1u;
    return (bit_hi != bit_lo) ? (j ^ SWAP_MASK) : j;
}

__global__ void __launch_bounds__(THREADS)
swap_gate_real_kernel(const float* __restrict__ state_re,
                      float* __restrict__ out)
{
    const unsigned t = blockIdx.x * THREADS + threadIdx.x;
    const unsigned stride = BLOCKS * THREADS;              // float4 stride

    // Front-batch 4 independent loads (MLP=4), then 4 stores.
    unsigned e4[UNROLL];
    float4 v[UNROLL];
#pragma unroll
    for (int k = 0; k < UNROLL; k++) {
        unsigned t4 = t + (unsigned)k * stride;            // float4 index
        unsigned e = t4 * 4u;                              // float index
        unsigned b = e >> NUM_QUBITS;                      // batch row
        unsigned j = e & (NSTATE - 1u);                    // in-state index
        unsigned src = swap_src(j);
        e4[k] = e;
        v[k] = *reinterpret_cast<const float4*>(state_re + b * NSTATE + src);
    }
#pragma unroll
    for (int k = 0; k < UNROLL; k++) {
        *reinterpret_cast<float4*>(out + e4[k]) = v[k];
    }
}

extern "C" void kernel_launch(void* const* d_in, const int* in_sizes, int n_in,
                              void* d_out, int out_size)
{
    const float* state_re = (const float*)d_in[0];
    // d_in[1] = state_im, d_in[2] = M: dead inputs (output is real part only).
    float* out = (float*)d_out;
    swap_gate_real_kernel<<<BLOCKS, THREADS>>>(state_re, out);
}

// round 5
// speedup vs baseline: 2.1503x; 1.0466x over previous
#include <cuda_runtime.h>

// BuiltSWAP on qubits A=0, B=7 of a 13-qubit state, batch 64.
// Reference computes state @ M (M = SWAP permutation matrix); after the
// bit-index flip in _swap_matrix this is out[b, j] = state[b, swap_bits(j)]
// with bits 12 and 5 exchanged (SWAP is an involution). The harness output
// buffer is n float32 (complex64 reference coerced to float32 = real part),
// so only state_re is permuted; state_im and M (256 MB) are dead inputs.
//
// The swap mask 0x1020 touches only the low 13 bits, so it applies directly
// to the flat float index g = b*8192 + j (batch bits unaffected):
//   src_global(g) = g ^ (bit12(g) != bit5(g) ? 0x1020 : 0)
//
// Shape: 256 CTAs x 256 threads, each thread does exactly 2 independent
// front-batched float4 loads (65536 * 2 = 131072 float4 = 524288 floats,
// exact -> no bounds checks, no predication). All 148 SMs active.

#define BIT_HI 12
#define BIT_LO 5
#define SWAP_MASK ((1u << BIT_HI) | (1u << BIT_LO))  // 0x1020

#define THREADS 256
#define BLOCKS 256
#define STRIDE4 ((unsigned)(BLOCKS * THREADS))   // 65536 float4 stride

__device__ __forceinline__ unsigned swap_src_flat(unsigned g) {
    // g is a flat float index; exchange bits 12 and 5 (within the state row).
    unsigned diff = ((g >> BIT_HI) ^ (g >> BIT_LO)) & 1u;
    return g ^ (diff ? SWAP_MASK : 0u);
}

__global__ void __launch_bounds__(THREADS)
swap_gate_real_kernel(const float* __restrict__ state_re,
                      float* __restrict__ out)
{
    const unsigned t = blockIdx.x * THREADS + threadIdx.x;   // float4 idx 0
    const unsigned e0 = t * 4u;                              // flat float idx
    const unsigned e1 = (t + STRIDE4) * 4u;

    // Front-batch both independent loads (MLP=2), then store.
    const float4 v0 = *reinterpret_cast<const float4*>(state_re + swap_src_flat(e0));
    const float4 v1 = *reinterpret_cast<const float4*>(state_re + swap_src_flat(e1));

    *reinterpret_cast<float4*>(out + e0) = v0;
    *reinterpret_cast<float4*>(out + e1) = v1;
}

extern "C" void kernel_launch(void* const* d_in, const int* in_sizes, int n_in,
                              void* d_out, int out_size)
{
    const float* state_re = (const float*)d_in[0];
    // d_in[1] = state_im, d_in[2] = M: dead inputs (output is real part only).
    float* out = (float*)d_out;
    swap_gate_real_kernel<<<BLOCKS, THREADS>>>(state_re, out);
}

// round 8
// speedup vs baseline: 2.8425x; 1.3219x over previous
#include <cuda_runtime.h>

// BuiltSWAP on qubits A=0, B=7 of a 13-qubit state, batch 64.
// Reference computes state @ M (M = SWAP permutation matrix); after the
// bit-index flip in _swap_matrix this is out[b, j] = state[b, swap_bits(j)]
// with bits 12 and 5 exchanged (SWAP is an involution). The harness output
// buffer is n float32 (complex64 reference coerced to float32 = real part),
// so only state_re is permuted; state_im and M (256 MB) are dead inputs.
//
// The swap mask 0x1020 touches only the low 13 bits, so it applies directly
// to the flat float index g = b*8192 + j (batch bits unaffected):
//   src_global(g) = g ^ (bit12(g) != bit5(g) ? 0x1020 : 0)
//
// Shape experiments (ncu kernel dur): 512x256/MLP=1 4.10us > 256x256/MLP=2
// 4.38us > 128x256/MLP=4 4.70us -- resident warps win, per-thread MLP loses
// (kernel is ramp/latency-bound; T_ovh ~5000cyc is the floor). Use the
// max-warp shape: 512 CTAs x 256 threads, exactly one float4 per thread
// (131072 threads, exact coverage, no predication).

#define BIT_HI 12
#define BIT_LO 5
#define SWAP_MASK ((1u << BIT_HI) | (1u << BIT_LO))  // 0x1020

#define THREADS 256
#define BLOCKS 512   // 512*256 threads * 4 floats = 524288 floats. Exact.

__device__ __forceinline__ unsigned swap_src_flat(unsigned g) {
    // g is a flat float index; exchange bits 12 and 5 (within the state row).
    unsigned diff = ((g >> BIT_HI) ^ (g >> BIT_LO)) & 1u;
    return g ^ (diff ? SWAP_MASK : 0u);
}

__global__ void __launch_bounds__(THREADS)
swap_gate_real_kernel(const float* __restrict__ state_re,
                      float* __restrict__ out)
{
    const unsigned t = blockIdx.x * THREADS + threadIdx.x;  // float4 index
    const unsigned e = t * 4u;                              // flat float index
    const float4 v = *reinterpret_cast<const float4*>(state_re + swap_src_flat(e));
    *reinterpret_cast<float4*>(out + e) = v;
}

extern "C" void kernel_launch(void* const* d_in, const int* in_sizes, int n_in,
                              void* d_out, int out_size)
{
    const float* state_re = (const float*)d_in[0];
    // d_in[1] = state_im, d_in[2] = M: dead inputs (output is real part only).
    float* out = (float*)d_out;
    swap_gate_real_kernel<<<BLOCKS, THREADS>>>(state_re, out);
}